// round 12
// baseline (speedup 1.0000x reference)
#include <cuda_runtime.h>
#include <cuda_bf16.h>
#include <cstdint>

#define HID 2048
#define MLP 8192
#define BATCH 256
#define NELEM_A (BATCH*HID)
#define NELEM_T (BATCH*MLP)
#define SROW 40
// byte sizes (CTA tile 64x64, BK=32)
#define STAGE_A_BYTES (2*64*SROW*2)     // Ah+Al per stage = 10240
#define ALO_BYTES     (64*SROW*2)       // 5120
#define WB_BYTES      (64*SROW*2)       // 5120
#define LUT_BYTES     1024
#define GEMM_SMEM (LUT_BYTES + 4*STAGE_A_BYTES + 2*WB_BYTES + 2*64*4)

__device__ __align__(16) __nv_bfloat16 g_a_hi[NELEM_A];
__device__ __align__(16) __nv_bfloat16 g_a_lo[NELEM_A];
__device__ __align__(16) __nv_bfloat16 g_t_hi[NELEM_T];
__device__ __align__(16) __nv_bfloat16 g_t_lo[NELEM_T];
__device__ __align__(16) float g_gate[NELEM_T];
__device__ __align__(16) float g_part[4*NELEM_A];

__device__ __forceinline__ uint32_t pack_bf2(__nv_bfloat16 a, __nv_bfloat16 b) {
    return (uint32_t)__bfloat16_as_ushort(a) | ((uint32_t)__bfloat16_as_ushort(b) << 16);
}
__device__ __forceinline__ float fp4_decode(int n) {
    int m = n & 7;
    float mag;
    if (m == 0) mag = 0.0f;
    else if (m == 1) mag = 0.5f;
    else mag = (1.0f + 0.5f * (float)(m & 1)) * (float)(1 << ((m >> 1) - 1));
    return (n & 8) ? -mag : mag;
}
__device__ __forceinline__ float silu_f(float v) { return v / (1.0f + __expf(-v)); }
__device__ __forceinline__ void mma_bf16(float* c, const uint32_t* a, const uint32_t* b) {
    asm volatile(
        "mma.sync.aligned.m16n8k16.row.col.f32.bf16.bf16.f32 "
        "{%0,%1,%2,%3}, {%4,%5,%6,%7}, {%8,%9}, {%0,%1,%2,%3};\n"
        : "+f"(c[0]), "+f"(c[1]), "+f"(c[2]), "+f"(c[3])
        : "r"(a[0]), "r"(a[1]), "r"(a[2]), "r"(a[3]), "r"(b[0]), "r"(b[1]));
}
__device__ __forceinline__ void ldsm4(uint32_t* r, uint32_t addr) {
    asm volatile("ldmatrix.sync.aligned.m8n8.x4.shared.b16 {%0,%1,%2,%3}, [%4];"
                 : "=r"(r[0]), "=r"(r[1]), "=r"(r[2]), "=r"(r[3]) : "r"(addr));
}
__device__ __forceinline__ void cp16(uint32_t dst, const void* src) {
    asm volatile("cp.async.cg.shared.global [%0], [%1], 16;" :: "r"(dst), "l"(src));
}
#define CP_COMMIT() asm volatile("cp.async.commit_group;" ::: "memory")
#define CP_WAIT2()  asm volatile("cp.async.wait_group 2;" ::: "memory")

// GEMM: CTA tile 64(M) x 64(N), BK=32 (one scale block). 128 threads, 4 CTAs/SM.
// grid (N/64, BATCH/64, nsplit). A via 4-deep cp.async ring; W exact-bf16 staged
// 1 tile ahead; per-k-block fp32 scale folded post-MMA: acc += s[n]*part.
// mode 0: fp32 out (+ blockIdx.z*BATCH*ldN); mode 1: silu(gate)*acc -> bf16 hi/lo.
__global__ void __launch_bounds__(128, 4) gemm_kernel(
    const int* __restrict__ wp_base, const float* __restrict__ ws_base,
    const __nv_bfloat16* __restrict__ a_hi, const __nv_bfloat16* __restrict__ a_lo,
    float* __restrict__ out, int Ktot, int ldN, int mode,
    const float* __restrict__ gatebuf,
    __nv_bfloat16* __restrict__ t_hi, __nv_bfloat16* __restrict__ t_lo)
{
    extern __shared__ char smem[];
    uint32_t* lut = (uint32_t*)smem;                      // 256 x bf16x2 exact fp4 pairs
    char* ringp = smem + LUT_BYTES;
    __nv_bfloat16* wb[2];
    wb[0] = (__nv_bfloat16*)(ringp + 4*STAGE_A_BYTES);
    wb[1] = (__nv_bfloat16*)(ringp + 4*STAGE_A_BYTES + WB_BYTES);
    float* sc[2];
    sc[0] = (float*)(ringp + 4*STAGE_A_BYTES + 2*WB_BYTES);
    sc[1] = sc[0] + 64;
    const uint32_t ring_u = (uint32_t)__cvta_generic_to_shared(ringp);
    uint32_t wb_u[2];
    wb_u[0] = (uint32_t)__cvta_generic_to_shared(wb[0]);
    wb_u[1] = (uint32_t)__cvta_generic_to_shared(wb[1]);

    const int tid = threadIdx.x;
    const int n0 = blockIdx.x * 64;
    const int m0 = blockIdx.y * 64;
    const int klen = Ktot / gridDim.z;
    const int kb = blockIdx.z * klen;
    const int nt = klen >> 5;                 // 64 for all configs
    lut[tid] = pack_bf2(__float2bfloat16(fp4_decode(tid & 15)),
                        __float2bfloat16(fp4_decode(tid >> 4)));
    lut[tid + 128] = pack_bf2(__float2bfloat16(fp4_decode((tid + 128) & 15)),
                              __float2bfloat16(fp4_decode((tid + 128) >> 4)));

    // A staging: row r = tid>>1 (0..63), half q = tid&1 covers 16B chunks {2q,2q+1}
    const int r = tid >> 1, q = tid & 1;
    const __nv_bfloat16* gAh = a_hi + (size_t)(m0 + r) * Ktot + kb + q * 16;
    const __nv_bfloat16* gAl = a_lo + (size_t)(m0 + r) * Ktot + kb + q * 16;
    const uint32_t d0 = (uint32_t)(r * SROW + q * 16) * 2;       // chunk 2q
    const uint32_t d1 = d0 + 16;                                  // chunk 2q+1

    // W staging: row wn = tid>>1, half wc = tid&1 -> int4 chunks {2wc, 2wc+1}
    const int wn = tid >> 1, wc = tid & 1;
    const int* wp = wp_base + (size_t)(n0 + wn) * (Ktot >> 1) + (kb >> 1) + wc * 8;
    const float* wsp = ws_base + (size_t)(n0 + tid) * (Ktot >> 5) + (kb >> 5);

    const int warp = tid >> 5, lane = tid & 31;
    const int wm = warp >> 1, wnw = warp & 1;       // 2x2 warp grid
    const int g = lane >> 2, tt = lane & 3;
    const uint32_t a_off = (uint32_t)(((wm*32 + (lane & 15))*SROW + (lane >> 4)*8) * 2);
    const uint32_t b_off = (uint32_t)(((wnw*32 + ((lane >> 4) << 3) + (lane & 7))*SROW
                                      + ((lane >> 3) & 1)*8) * 2);
    const int sc_idx = wnw*32 + 2*tt;

    float acc[32];
#pragma unroll
    for (int i = 0; i < 32; ++i) acc[i] = 0.f;

    // ---- prologue: cp.async tiles 0,1,2 ----
#pragma unroll
    for (int t = 0; t < 3; ++t) {
        const uint32_t sb = ring_u + (uint32_t)t * STAGE_A_BYTES;
        const int off = t * 32;
        cp16(sb + d0, gAh + off);
        cp16(sb + d1, gAh + off + 8);
        cp16(sb + ALO_BYTES + d0, gAl + off);
        cp16(sb + ALO_BYTES + d1, gAl + off + 8);
        CP_COMMIT();
    }
    // W regs for tiles 0 and 1 (8 ints = 16 fp4-pairs per thread per tile)
    int4  rW1a = *(const int4*)wp;
    int4  rW1b = *(const int4*)(wp + 4);
    float rS1  = (tid < 64) ? wsp[0] : 0.f;
    int4  rW2a = (nt > 1) ? *(const int4*)(wp + 16) : rW1a;
    int4  rW2b = (nt > 1) ? *(const int4*)(wp + 20) : rW1b;
    float rS2  = (tid < 64 && nt > 1) ? wsp[1] : rS1;

    CP_WAIT2();
    __syncthreads();      // lut ready
    {
        char* dstw = (char*)wb[0] + (wn*SROW + wc*16)*2;
        *(uint4*)dstw = make_uint4(lut[rW1a.x & 255], lut[rW1a.y & 255],
                                   lut[rW1a.z & 255], lut[rW1a.w & 255]);
        *(uint4*)(dstw + 16) = make_uint4(lut[rW1b.x & 255], lut[rW1b.y & 255],
                                          lut[rW1b.z & 255], lut[rW1b.w & 255]);
        if (tid < 64) sc[0][tid] = rS1;
        rW1a = rW2a; rW1b = rW2b; rS1 = rS2;
    }

    for (int it = 0; it < nt; ++it) {
        CP_WAIT2();
        __syncthreads();   // stage(it) arrived + wb(it&1)/sc(it&1) staged
        const int j = it + 3;
        if (j < nt) {
            const uint32_t sb = ring_u + (uint32_t)(j & 3) * STAGE_A_BYTES;
            const int off = j * 32;
            cp16(sb + d0, gAh + off);
            cp16(sb + d1, gAh + off + 8);
            cp16(sb + ALO_BYTES + d0, gAl + off);
            cp16(sb + ALO_BYTES + d1, gAl + off + 8);
        }
        CP_COMMIT();
        if (it + 2 < nt) {
            rW2a = *(const int4*)(wp + (it + 2) * 16);
            rW2b = *(const int4*)(wp + (it + 2) * 16 + 4);
            if (tid < 64) rS2 = wsp[it + 2];
        }

        const uint32_t u = ring_u + (uint32_t)(it & 3) * STAGE_A_BYTES;
        const uint32_t wbu = wb_u[it & 1];
        float part[32];
#pragma unroll
        for (int i = 0; i < 32; ++i) part[i] = 0.f;
#pragma unroll
        for (int ks = 0; ks < 2; ++ks) {
            const uint32_t kso = (uint32_t)(ks*16*2);
            uint32_t ah[2][4], al[2][4];
#pragma unroll
            for (int mi = 0; mi < 2; ++mi) {
                const uint32_t mo = (uint32_t)(mi*16*SROW*2);
                ldsm4(ah[mi], u + a_off + mo + kso);
                ldsm4(al[mi], u + (uint32_t)ALO_BYTES + a_off + mo + kso);
            }
            uint32_t bw[2][4];
#pragma unroll
            for (int gb = 0; gb < 2; ++gb) {
                const uint32_t go = (uint32_t)(gb*16*SROW*2);
                ldsm4(bw[gb], wbu + b_off + go + kso);
            }
#pragma unroll
            for (int ni = 0; ni < 4; ++ni) {
                const uint32_t* pb = &bw[ni >> 1][(ni & 1)*2];
#pragma unroll
                for (int mi = 0; mi < 2; ++mi) {
                    float* p = part + mi*16 + ni*4;
                    mma_bf16(p, ah[mi], pb);   // Ah * W
                    mma_bf16(p, al[mi], pb);   // Al * W
                }
            }
        }
        const float* scp = sc[it & 1];
#pragma unroll
        for (int ni = 0; ni < 4; ++ni) {
            float2 sv = *(const float2*)(scp + sc_idx + ni*8);
#pragma unroll
            for (int mi = 0; mi < 2; ++mi) {
                float* c = acc + mi*16 + ni*4;
                const float* p = part + mi*16 + ni*4;
                c[0] = fmaf(sv.x, p[0], c[0]);
                c[1] = fmaf(sv.y, p[1], c[1]);
                c[2] = fmaf(sv.x, p[2], c[2]);
                c[3] = fmaf(sv.y, p[3], c[3]);
            }
        }
        if (it + 1 < nt) {
            char* dstw = (char*)wb[(it + 1) & 1] + (wn*SROW + wc*16)*2;
            *(uint4*)dstw = make_uint4(lut[rW1a.x & 255], lut[rW1a.y & 255],
                                       lut[rW1a.z & 255], lut[rW1a.w & 255]);
            *(uint4*)(dstw + 16) = make_uint4(lut[rW1b.x & 255], lut[rW1b.y & 255],
                                              lut[rW1b.z & 255], lut[rW1b.w & 255]);
            if (tid < 64) sc[(it + 1) & 1][tid] = rS1;
            rW1a = rW2a; rW1b = rW2b; rS1 = rS2;
        }
    }

    if (mode == 1) {
#pragma unroll
        for (int mi = 0; mi < 2; ++mi)
#pragma unroll
            for (int ni = 0; ni < 4; ++ni) {
                const float* c = acc + mi*16 + ni*4;
                int r0 = m0 + wm*32 + mi*16 + g;
                int jj = n0 + wnw*32 + ni*8 + 2*tt;
                {
                    float t0 = silu_f(gatebuf[(size_t)r0*ldN + jj])     * c[0];
                    float t1 = silu_f(gatebuf[(size_t)r0*ldN + jj + 1]) * c[1];
                    __nv_bfloat16 h0 = __float2bfloat16(t0), h1 = __float2bfloat16(t1);
                    *(uint32_t*)(t_hi + (size_t)r0*ldN + jj) = pack_bf2(h0, h1);
                    *(uint32_t*)(t_lo + (size_t)r0*ldN + jj) =
                        pack_bf2(__float2bfloat16(t0 - __bfloat162float(h0)),
                                 __float2bfloat16(t1 - __bfloat162float(h1)));
                }
                {
                    int r1 = r0 + 8;
                    float t2 = silu_f(gatebuf[(size_t)r1*ldN + jj])     * c[2];
                    float t3 = silu_f(gatebuf[(size_t)r1*ldN + jj + 1]) * c[3];
                    __nv_bfloat16 h2 = __float2bfloat16(t2), h3 = __float2bfloat16(t3);
                    *(uint32_t*)(t_hi + (size_t)r1*ldN + jj) = pack_bf2(h2, h3);
                    *(uint32_t*)(t_lo + (size_t)r1*ldN + jj) =
                        pack_bf2(__float2bfloat16(t2 - __bfloat162float(h2)),
                                 __float2bfloat16(t3 - __bfloat162float(h3)));
                }
            }
    } else {
        float* po = out + (size_t)blockIdx.z * BATCH * ldN;
#pragma unroll
        for (int mi = 0; mi < 2; ++mi)
#pragma unroll
            for (int ni = 0; ni < 4; ++ni) {
                const float* c = acc + mi*16 + ni*4;
                int r0 = m0 + wm*32 + mi*16 + g;
                int jj = n0 + wnw*32 + ni*8 + 2*tt;
                *(float2*)(po + (size_t)r0*ldN + jj)     = make_float2(c[0], c[1]);
                *(float2*)(po + (size_t)(r0+8)*ldN + jj) = make_float2(c[2], c[3]);
            }
    }
}

__global__ void split_x_kernel(const float* __restrict__ x) {
    int i = blockIdx.x * 256 + threadIdx.x;
    float v = x[i];
    __nv_bfloat16 h = __float2bfloat16(v);
    g_a_hi[i] = h;
    g_a_lo[i] = __float2bfloat16(v - __bfloat162float(h));
}

__global__ void reduce_split_kernel(float* __restrict__ out, int final_layer) {
    int i = blockIdx.x * 256 + threadIdx.x;
    float s = g_part[i] + g_part[i + NELEM_A] + g_part[i + 2*NELEM_A] + g_part[i + 3*NELEM_A];
    if (final_layer) {
        out[i] = s;
    } else {
        __nv_bfloat16 h = __float2bfloat16(s);
        g_a_hi[i] = h;
        g_a_lo[i] = __float2bfloat16(s - __bfloat162float(h));
    }
}

extern "C" void kernel_launch(void* const* d_in, const int* in_sizes, int n_in,
                              void* d_out, int out_size) {
    const float* x  = (const float*)d_in[0];
    const int*   gp = (const int*)d_in[1];
    const float* gs = (const float*)d_in[2];
    const int*   up = (const int*)d_in[3];
    const float* us = (const float*)d_in[4];
    const int*   dp = (const int*)d_in[5];
    const float* ds = (const float*)d_in[6];
    float* out = (float*)d_out;

    cudaFuncSetAttribute(gemm_kernel, cudaFuncAttributeMaxDynamicSharedMemorySize, GEMM_SMEM);

    void *p_ah, *p_al, *p_th, *p_tl, *p_g, *p_part;
    cudaGetSymbolAddress(&p_ah, g_a_hi);
    cudaGetSymbolAddress(&p_al, g_a_lo);
    cudaGetSymbolAddress(&p_th, g_t_hi);
    cudaGetSymbolAddress(&p_tl, g_t_lo);
    cudaGetSymbolAddress(&p_g, g_gate);
    cudaGetSymbolAddress(&p_part, g_part);

    split_x_kernel<<<NELEM_A/256, 256>>>(x);

    for (int l = 0; l < 18; ++l) {
        const size_t woff  = (size_t)l * MLP * (HID/2);
        const size_t soff  = (size_t)l * MLP * (HID/32);
        const size_t dwoff = (size_t)l * HID * (MLP/2);
        const size_t dsoff = (size_t)l * HID * (MLP/32);

        gemm_kernel<<<dim3(MLP/64, BATCH/64, 1), 128, GEMM_SMEM>>>(
            gp + woff, gs + soff,
            (const __nv_bfloat16*)p_ah, (const __nv_bfloat16*)p_al,
            (float*)p_g, HID, MLP, 0, nullptr, nullptr, nullptr);
        gemm_kernel<<<dim3(MLP/64, BATCH/64, 1), 128, GEMM_SMEM>>>(
            up + woff, us + soff,
            (const __nv_bfloat16*)p_ah, (const __nv_bfloat16*)p_al,
            nullptr, HID, MLP, 1, (const float*)p_g,
            (__nv_bfloat16*)p_th, (__nv_bfloat16*)p_tl);
        gemm_kernel<<<dim3(HID/64, BATCH/64, 4), 128, GEMM_SMEM>>>(
            dp + dwoff, ds + dsoff,
            (const __nv_bfloat16*)p_th, (const __nv_bfloat16*)p_tl,
            (float*)p_part, MLP, HID, 0, nullptr, nullptr, nullptr);
        reduce_split_kernel<<<NELEM_A/256, 256>>>(out, l == 17 ? 1 : 0);
    }
}

// round 13
// speedup vs baseline: 1.3612x; 1.3612x over previous
#include <cuda_runtime.h>
#include <cuda_bf16.h>
#include <cstdint>

#define HID 2048
#define MLP 8192
#define BATCH 256
#define NELEM_A (BATCH*HID)
#define NELEM_T (BATCH*MLP)
#define SROW 40
// byte sizes (CTA tile 128x64, BK=32)
#define STAGE_A_BYTES (2*128*SROW*2)    // Ah+Al per stage = 20480
#define ALO_BYTES     (128*SROW*2)      // 10240
#define WB_BYTES      (64*SROW*2)       // 5120 per W slot
#define LUT_BYTES     1024
// lut | 4 A stages | 4 W slots | 4 x 64 scale floats
#define GEMM_SMEM (LUT_BYTES + 4*STAGE_A_BYTES + 4*WB_BYTES + 4*64*4)

__device__ __align__(16) __nv_bfloat16 g_a_hi[NELEM_A];
__device__ __align__(16) __nv_bfloat16 g_a_lo[NELEM_A];
__device__ __align__(16) __nv_bfloat16 g_t_hi[NELEM_T];
__device__ __align__(16) __nv_bfloat16 g_t_lo[NELEM_T];
__device__ __align__(16) float g_gate[NELEM_T];
__device__ __align__(16) float g_part[4*NELEM_A];

__device__ __forceinline__ uint32_t pack_bf2(__nv_bfloat16 a, __nv_bfloat16 b) {
    return (uint32_t)__bfloat16_as_ushort(a) | ((uint32_t)__bfloat16_as_ushort(b) << 16);
}
__device__ __forceinline__ float fp4_decode(int n) {
    int m = n & 7;
    float mag;
    if (m == 0) mag = 0.0f;
    else if (m == 1) mag = 0.5f;
    else mag = (1.0f + 0.5f * (float)(m & 1)) * (float)(1 << ((m >> 1) - 1));
    return (n & 8) ? -mag : mag;
}
__device__ __forceinline__ float silu_f(float v) { return v / (1.0f + __expf(-v)); }
__device__ __forceinline__ void mma_bf16(float* c, const uint32_t* a, const uint32_t* b) {
    asm volatile(
        "mma.sync.aligned.m16n8k16.row.col.f32.bf16.bf16.f32 "
        "{%0,%1,%2,%3}, {%4,%5,%6,%7}, {%8,%9}, {%0,%1,%2,%3};\n"
        : "+f"(c[0]), "+f"(c[1]), "+f"(c[2]), "+f"(c[3])
        : "r"(a[0]), "r"(a[1]), "r"(a[2]), "r"(a[3]), "r"(b[0]), "r"(b[1]));
}
__device__ __forceinline__ void ldsm4(uint32_t* r, uint32_t addr) {
    asm volatile("ldmatrix.sync.aligned.m8n8.x4.shared.b16 {%0,%1,%2,%3}, [%4];"
                 : "=r"(r[0]), "=r"(r[1]), "=r"(r[2]), "=r"(r[3]) : "r"(addr));
}
__device__ __forceinline__ void cp16(uint32_t dst, const void* src) {
    asm volatile("cp.async.cg.shared.global [%0], [%1], 16;" :: "r"(dst), "l"(src));
}
#define CP_COMMIT() asm volatile("cp.async.commit_group;" ::: "memory")
#define CP_WAIT0()  asm volatile("cp.async.wait_group 0;" ::: "memory")

// GEMM: CTA tile 128(M) x 64(N), BK=32 (one scale block). 256 threads, 2 CTAs/SM.
// Pairwise pipeline: 2 k-tiles per iteration, ONE barrier + ONE cp.async wait per pair.
// A: 4-stage cp.async ring (one pair in flight). W: exact-bf16 dequant, 4-slot ring,
// staged one pair ahead. Per-k-block fp32 scale folded post-MMA: acc += s[n]*part.
// mode 0: fp32 out (+ blockIdx.z*BATCH*ldN); mode 1: silu(gate)*acc -> bf16 hi/lo.
__global__ void __launch_bounds__(256, 2) gemm_kernel(
    const int* __restrict__ wp_base, const float* __restrict__ ws_base,
    const __nv_bfloat16* __restrict__ a_hi, const __nv_bfloat16* __restrict__ a_lo,
    float* __restrict__ out, int Ktot, int ldN, int mode,
    const float* __restrict__ gatebuf,
    __nv_bfloat16* __restrict__ t_hi, __nv_bfloat16* __restrict__ t_lo)
{
    extern __shared__ char smem[];
    uint32_t* lut = (uint32_t*)smem;                 // 256 x bf16x2 exact fp4 pairs
    char* ringp = smem + LUT_BYTES;                  // 4 A stages
    char* wbp   = ringp + 4*STAGE_A_BYTES;           // 4 W slots
    float* scb  = (float*)(wbp + 4*WB_BYTES);        // 4 x 64 scales
    const uint32_t ring_u = (uint32_t)__cvta_generic_to_shared(ringp);
    const uint32_t wb_u   = (uint32_t)__cvta_generic_to_shared(wbp);

    const int tid = threadIdx.x;
    const int n0 = blockIdx.x * 64;
    const int m0 = blockIdx.y * 128;
    const int klen = Ktot / gridDim.z;
    const int kb = blockIdx.z * klen;
    const int npair = klen >> 6;              // 32 pairs (64 tiles) for all configs
    lut[tid] = pack_bf2(__float2bfloat16(fp4_decode(tid & 15)),
                        __float2bfloat16(fp4_decode(tid >> 4)));

    // A staging map: 4 lanes per row; thread covers rows r and r+64, 16B chunk q
    const int r = tid >> 2, q = tid & 3;
    const __nv_bfloat16* gAh = a_hi + (size_t)(m0 + r) * Ktot + kb + q * 8;
    const __nv_bfloat16* gAl = a_lo + (size_t)(m0 + r) * Ktot + kb + q * 8;
    const size_t rowskip = (size_t)64 * Ktot;
    const uint32_t d0 = (uint32_t)(r * SROW + q * 8) * 2;
    const uint32_t d1 = (uint32_t)((r + 64) * SROW + q * 8) * 2;

    // W map: row wn, 4 packed ints (8 bf16) at chunk wc
    const int wn = tid >> 2, wc = tid & 3;
    const int* wp = wp_base + (size_t)(n0 + wn) * (Ktot >> 1) + (kb >> 1) + wc * 4;
    const float* wsp = ws_base + (size_t)(n0 + tid) * (Ktot >> 5) + (kb >> 5);
    const uint32_t wdst = (uint32_t)(wn*SROW + wc*8) * 2;

    const int warp = tid >> 5, lane = tid & 31;
    const int wm = warp >> 1, wnw = warp & 1;
    const int g = lane >> 2, tt = lane & 3;
    const uint32_t a_off = (uint32_t)(((wm*32 + (lane & 15))*SROW + (lane >> 4)*8) * 2);
    const uint32_t b_off = (uint32_t)(((wnw*32 + ((lane >> 4) << 3) + (lane & 7))*SROW
                                      + ((lane >> 3) & 1)*8) * 2);
    const int sc_idx = wnw*32 + 2*tt;

    float acc[32];
#pragma unroll
    for (int i = 0; i < 32; ++i) acc[i] = 0.f;

    // ---- prologue ----
    // A pair 0 (tiles 0,1 -> slots 0,1)
#pragma unroll
    for (int t = 0; t < 2; ++t) {
        const uint32_t sb = ring_u + (uint32_t)t * STAGE_A_BYTES;
        const int off = t * 32;
        cp16(sb + d0, gAh + off);
        cp16(sb + d1, gAh + rowskip + off);
        cp16(sb + ALO_BYTES + d0, gAl + off);
        cp16(sb + ALO_BYTES + d1, gAl + rowskip + off);
    }
    CP_COMMIT();
    // W regs: pair 0 (tiles 0,1) now, pair 1 (tiles 2,3) held
    int4 wv0 = *(const int4*)wp;
    int4 wv1 = *(const int4*)(wp + 16);
    int4 wh0 = *(const int4*)(wp + 32);
    int4 wh1 = *(const int4*)(wp + 48);
    float sv0 = 0.f, sv1 = 0.f, sh0 = 0.f, sh1 = 0.f;
    if (tid < 64) { sv0 = wsp[0]; sv1 = wsp[1]; sh0 = wsp[2]; sh1 = wsp[3]; }

    __syncthreads();   // lut visible
    // stage W pair 0 into slots 0,1
    *(uint4*)(wbp + 0*WB_BYTES + wdst) =
        make_uint4(lut[wv0.x & 255], lut[wv0.y & 255], lut[wv0.z & 255], lut[wv0.w & 255]);
    *(uint4*)(wbp + 1*WB_BYTES + wdst) =
        make_uint4(lut[wv1.x & 255], lut[wv1.y & 255], lut[wv1.z & 255], lut[wv1.w & 255]);
    if (tid < 64) { scb[0*64 + tid] = sv0; scb[1*64 + tid] = sv1; }

    for (int p = 0; p < npair; ++p) {
        CP_WAIT0();
        __syncthreads();    // A pair p arrived; W slots (pair p) staged; prev reads done
        // issue A pair p+1 (slots (2p+2)&3,(2p+3)&3 — last read at iter p-1)
        if (p + 1 < npair) {
#pragma unroll
            for (int h = 0; h < 2; ++h) {
                const int t = 2*p + 2 + h;
                const uint32_t sb = ring_u + (uint32_t)(t & 3) * STAGE_A_BYTES;
                const int off = t * 32;
                cp16(sb + d0, gAh + off);
                cp16(sb + d1, gAh + rowskip + off);
                cp16(sb + ALO_BYTES + d0, gAl + off);
                cp16(sb + ALO_BYTES + d1, gAl + rowskip + off);
            }
            // stage W pair p+1 from held regs into slots (2p+2)&3,(2p+3)&3
            *(uint4*)(wbp + (uint32_t)((2*p+2) & 3)*WB_BYTES + wdst) =
                make_uint4(lut[wh0.x & 255], lut[wh0.y & 255],
                           lut[wh0.z & 255], lut[wh0.w & 255]);
            *(uint4*)(wbp + (uint32_t)((2*p+3) & 3)*WB_BYTES + wdst) =
                make_uint4(lut[wh1.x & 255], lut[wh1.y & 255],
                           lut[wh1.z & 255], lut[wh1.w & 255]);
            if (tid < 64) {
                scb[((2*p+2) & 3)*64 + tid] = sh0;
                scb[((2*p+3) & 3)*64 + tid] = sh1;
            }
        }
        CP_COMMIT();
        // prefetch W pair p+2
        if (p + 2 < npair) {
            wh0 = *(const int4*)(wp + (2*p + 4) * 16);
            wh1 = *(const int4*)(wp + (2*p + 5) * 16);
            if (tid < 64) { sh0 = wsp[2*p + 4]; sh1 = wsp[2*p + 5]; }
        }

        // compute tiles 2p and 2p+1
#pragma unroll
        for (int h = 0; h < 2; ++h) {
            const int t = 2*p + h;
            const uint32_t u = ring_u + (uint32_t)(t & 3) * STAGE_A_BYTES;
            const uint32_t wbu = wb_u + (uint32_t)(t & 3) * WB_BYTES;
            float part[32];
#pragma unroll
            for (int i = 0; i < 32; ++i) part[i] = 0.f;
#pragma unroll
            for (int ks = 0; ks < 2; ++ks) {
                const uint32_t kso = (uint32_t)(ks*16*2);
                uint32_t ah[2][4], al[2][4];
#pragma unroll
                for (int mi = 0; mi < 2; ++mi) {
                    const uint32_t mo = (uint32_t)(mi*16*SROW*2);
                    ldsm4(ah[mi], u + a_off + mo + kso);
                    ldsm4(al[mi], u + (uint32_t)ALO_BYTES + a_off + mo + kso);
                }
                uint32_t bw[2][4];
#pragma unroll
                for (int gb = 0; gb < 2; ++gb) {
                    const uint32_t go = (uint32_t)(gb*16*SROW*2);
                    ldsm4(bw[gb], wbu + b_off + go + kso);
                }
#pragma unroll
                for (int ni = 0; ni < 4; ++ni) {
                    const uint32_t* pb = &bw[ni >> 1][(ni & 1)*2];
#pragma unroll
                    for (int mi = 0; mi < 2; ++mi) {
                        float* pp = part + mi*16 + ni*4;
                        mma_bf16(pp, ah[mi], pb);   // Ah * W
                        mma_bf16(pp, al[mi], pb);   // Al * W
                    }
                }
            }
            const float* scp = scb + (t & 3)*64;
#pragma unroll
            for (int ni = 0; ni < 4; ++ni) {
                float2 sv = *(const float2*)(scp + sc_idx + ni*8);
#pragma unroll
                for (int mi = 0; mi < 2; ++mi) {
                    float* c = acc + mi*16 + ni*4;
                    const float* pp = part + mi*16 + ni*4;
                    c[0] = fmaf(sv.x, pp[0], c[0]);
                    c[1] = fmaf(sv.y, pp[1], c[1]);
                    c[2] = fmaf(sv.x, pp[2], c[2]);
                    c[3] = fmaf(sv.y, pp[3], c[3]);
                }
            }
        }
    }

    if (mode == 1) {
#pragma unroll
        for (int mi = 0; mi < 2; ++mi)
#pragma unroll
            for (int ni = 0; ni < 4; ++ni) {
                const float* c = acc + mi*16 + ni*4;
                int r0 = m0 + wm*32 + mi*16 + g;
                int jj = n0 + wnw*32 + ni*8 + 2*tt;
                {
                    float t0 = silu_f(gatebuf[(size_t)r0*ldN + jj])     * c[0];
                    float t1 = silu_f(gatebuf[(size_t)r0*ldN + jj + 1]) * c[1];
                    __nv_bfloat16 h0 = __float2bfloat16(t0), h1 = __float2bfloat16(t1);
                    *(uint32_t*)(t_hi + (size_t)r0*ldN + jj) = pack_bf2(h0, h1);
                    *(uint32_t*)(t_lo + (size_t)r0*ldN + jj) =
                        pack_bf2(__float2bfloat16(t0 - __bfloat162float(h0)),
                                 __float2bfloat16(t1 - __bfloat162float(h1)));
                }
                {
                    int r1 = r0 + 8;
                    float t2 = silu_f(gatebuf[(size_t)r1*ldN + jj])     * c[2];
                    float t3 = silu_f(gatebuf[(size_t)r1*ldN + jj + 1]) * c[3];
                    __nv_bfloat16 h2 = __float2bfloat16(t2), h3 = __float2bfloat16(t3);
                    *(uint32_t*)(t_hi + (size_t)r1*ldN + jj) = pack_bf2(h2, h3);
                    *(uint32_t*)(t_lo + (size_t)r1*ldN + jj) =
                        pack_bf2(__float2bfloat16(t2 - __bfloat162float(h2)),
                                 __float2bfloat16(t3 - __bfloat162float(h3)));
                }
            }
    } else {
        float* po = out + (size_t)blockIdx.z * BATCH * ldN;
#pragma unroll
        for (int mi = 0; mi < 2; ++mi)
#pragma unroll
            for (int ni = 0; ni < 4; ++ni) {
                const float* c = acc + mi*16 + ni*4;
                int r0 = m0 + wm*32 + mi*16 + g;
                int jj = n0 + wnw*32 + ni*8 + 2*tt;
                *(float2*)(po + (size_t)r0*ldN + jj)     = make_float2(c[0], c[1]);
                *(float2*)(po + (size_t)(r0+8)*ldN + jj) = make_float2(c[2], c[3]);
            }
    }
}

__global__ void split_x_kernel(const float* __restrict__ x) {
    int i = blockIdx.x * 256 + threadIdx.x;
    float v = x[i];
    __nv_bfloat16 h = __float2bfloat16(v);
    g_a_hi[i] = h;
    g_a_lo[i] = __float2bfloat16(v - __bfloat162float(h));
}

__global__ void reduce_split_kernel(float* __restrict__ out, int final_layer) {
    int i = blockIdx.x * 256 + threadIdx.x;
    float s = g_part[i] + g_part[i + NELEM_A] + g_part[i + 2*NELEM_A] + g_part[i + 3*NELEM_A];
    if (final_layer) {
        out[i] = s;
    } else {
        __nv_bfloat16 h = __float2bfloat16(s);
        g_a_hi[i] = h;
        g_a_lo[i] = __float2bfloat16(s - __bfloat162float(h));
    }
}

extern "C" void kernel_launch(void* const* d_in, const int* in_sizes, int n_in,
                              void* d_out, int out_size) {
    const float* x  = (const float*)d_in[0];
    const int*   gp = (const int*)d_in[1];
    const float* gs = (const float*)d_in[2];
    const int*   up = (const int*)d_in[3];
    const float* us = (const float*)d_in[4];
    const int*   dp = (const int*)d_in[5];
    const float* ds = (const float*)d_in[6];
    float* out = (float*)d_out;

    cudaFuncSetAttribute(gemm_kernel, cudaFuncAttributeMaxDynamicSharedMemorySize, GEMM_SMEM);

    void *p_ah, *p_al, *p_th, *p_tl, *p_g, *p_part;
    cudaGetSymbolAddress(&p_ah, g_a_hi);
    cudaGetSymbolAddress(&p_al, g_a_lo);
    cudaGetSymbolAddress(&p_th, g_t_hi);
    cudaGetSymbolAddress(&p_tl, g_t_lo);
    cudaGetSymbolAddress(&p_g, g_gate);
    cudaGetSymbolAddress(&p_part, g_part);

    split_x_kernel<<<NELEM_A/256, 256>>>(x);

    for (int l = 0; l < 18; ++l) {
        const size_t woff  = (size_t)l * MLP * (HID/2);
        const size_t soff  = (size_t)l * MLP * (HID/32);
        const size_t dwoff = (size_t)l * HID * (MLP/2);
        const size_t dsoff = (size_t)l * HID * (MLP/32);

        gemm_kernel<<<dim3(MLP/64, 2, 1), 256, GEMM_SMEM>>>(
            gp + woff, gs + soff,
            (const __nv_bfloat16*)p_ah, (const __nv_bfloat16*)p_al,
            (float*)p_g, HID, MLP, 0, nullptr, nullptr, nullptr);
        gemm_kernel<<<dim3(MLP/64, 2, 1), 256, GEMM_SMEM>>>(
            up + woff, us + soff,
            (const __nv_bfloat16*)p_ah, (const __nv_bfloat16*)p_al,
            nullptr, HID, MLP, 1, (const float*)p_g,
            (__nv_bfloat16*)p_th, (__nv_bfloat16*)p_tl);
        gemm_kernel<<<dim3(HID/64, 2, 4), 256, GEMM_SMEM>>>(
            dp + dwoff, ds + dsoff,
            (const __nv_bfloat16*)p_th, (const __nv_bfloat16*)p_tl,
            (float*)p_part, MLP, HID, 0, nullptr, nullptr, nullptr);
        reduce_split_kernel<<<NELEM_A/256, 256>>>(out, l == 17 ? 1 : 0);
    }
}